// round 9
// baseline (speedup 1.0000x reference)
#include <cuda_runtime.h>
#include <cuda_bf16.h>
#include <cstdint>
#include <math.h>

#define BHN 64
#define NS  1024
#define DD  64

// ---------------- helpers ----------------
__device__ __forceinline__ uint32_t smem_u32(const void* p) {
    uint32_t a;
    asm("{ .reg .u64 t; cvta.to.shared.u64 t, %1; cvt.u32.u64 %0, t; }" : "=r"(a) : "l"(p));
    return a;
}
// split two floats into bf16 hi/lo packed pairs
__device__ __forceinline__ void split2(float a, float b, uint32_t& hi, uint32_t& lo) {
    __nv_bfloat16 ha = __float2bfloat16_rn(a), hb = __float2bfloat16_rn(b);
    float ra = a - __bfloat162float(ha);
    float rb = b - __bfloat162float(hb);
    __nv_bfloat162 H; H.x = ha; H.y = hb;
    __nv_bfloat162 L; L.x = __float2bfloat16_rn(ra); L.y = __float2bfloat16_rn(rb);
    hi = *reinterpret_cast<uint32_t*>(&H);
    lo = *reinterpret_cast<uint32_t*>(&L);
}

// 64-half rows (128B), 8 chunks of 16B, XOR-swizzled by row%8
__device__ __forceinline__ uint32_t off64(int row, int halfcol) {
    return (uint32_t)((row << 7) + ((((halfcol >> 3) ^ (row & 7)) << 4) | ((halfcol & 7) << 1)));
}

__device__ __forceinline__ void ldsm4(uint32_t (&r)[4], uint32_t addr) {
    asm volatile("ldmatrix.sync.aligned.m8n8.x4.shared.b16 {%0,%1,%2,%3}, [%4];"
                 : "=r"(r[0]), "=r"(r[1]), "=r"(r[2]), "=r"(r[3]) : "r"(addr));
}
__device__ __forceinline__ void ldsm4t(uint32_t (&r)[4], uint32_t addr) {
    asm volatile("ldmatrix.sync.aligned.m8n8.x4.trans.shared.b16 {%0,%1,%2,%3}, [%4];"
                 : "=r"(r[0]), "=r"(r[1]), "=r"(r[2]), "=r"(r[3]) : "r"(addr));
}
__device__ __forceinline__ void mma16816(float* c, const uint32_t (&a)[4], uint32_t b0, uint32_t b1) {
    asm volatile(
        "mma.sync.aligned.m16n8k16.row.col.f32.bf16.bf16.f32 "
        "{%0,%1,%2,%3}, {%4,%5,%6,%7}, {%8,%9}, {%0,%1,%2,%3};"
        : "+f"(c[0]), "+f"(c[1]), "+f"(c[2]), "+f"(c[3])
        : "r"(a[0]), "r"(a[1]), "r"(a[2]), "r"(a[3]), "r"(b0), "r"(b1));
}

// load a 64x64 f32 tile, split to bf16 hi/lo, store swizzled (256 threads)
__device__ __forceinline__ void load_split64x64(const float* __restrict__ g,
                                                char* smH, char* smL, int t) {
    const float4* p = (const float4*)g;
    #pragma unroll
    for (int c = 0; c < 4; ++c) {
        int idx = (c << 8) + t;            // 1024 float4
        float4 x = p[idx];
        int row = idx >> 4, d0 = (idx & 15) << 2;
        uint32_t h0, l0, h1, l1;
        split2(x.x, x.y, h0, l0);
        split2(x.z, x.w, h1, l1);
        uint32_t o = off64(row, d0);
        *reinterpret_cast<uint2*>(smH + o) = make_uint2(h0, h1);
        *reinterpret_cast<uint2*>(smL + o) = make_uint2(l0, l1);
    }
}

// smem map (bytes): Q 0/8192, K 16384/24576, V 32768/40960, P 49152/57344,
// smM 65536, smI 65792, sRed 66048, sSum 67072; end 68096 (+pad)
#define F_SMEM (68096 + 1024)

// ---------------------------------------------------------------------------
// Fused attention: per CTA = (bh, 64 query rows).
// Pass 1: per 64-col j-step: QK^T (bf16 3-pass) -> scores write; block-wide
//         running max; p~ = exp(s - m_run) -> bf16 smem; flash-rescaled
//         ctx += p~ @ V (bf16 3-pass).  Stats finalized in smem.
// Pass 2: stream own scores slice (L1/L2-hot) -> attn.
// ---------------------------------------------------------------------------
__global__ void __launch_bounds__(256, 3)
fused_attn(const float* __restrict__ qg, const float* __restrict__ kg,
           const float* __restrict__ vg, float* __restrict__ scores,
           float* __restrict__ attn, float* __restrict__ ctx)
{
    extern __shared__ char dsm_raw[];
    char* smb = (char*)(((uintptr_t)dsm_raw + 1023) & ~(uintptr_t)1023);

    const int t = threadIdx.x, lane = t & 31, wid = t >> 5;
    const int wm = wid >> 2, wn = wid & 3;
    const int bh = blockIdx.y, i0 = blockIdx.x << 6;

    char* sQH = smb;
    char* sQL = smb + 8192;
    char* sKH = smb + 16384;
    char* sKL = smb + 24576;
    char* sVH = smb + 32768;
    char* sVL = smb + 40960;
    char* sPH = smb + 49152;
    char* sPL = smb + 57344;
    float* smM  = (float*)(smb + 65536);   // [64] final row max
    float* smI  = (float*)(smb + 65792);   // [64] final 1/sum
    float* sRed = (float*)(smb + 66048);   // [4][64] per-step max reduce
    float* sSum = (float*)(smb + 67072);   // [4][64] final sum reduce

    const uint32_t uQH = smem_u32(sQH), uQL = smem_u32(sQL);
    const uint32_t uKH = smem_u32(sKH), uKL = smem_u32(sKL);
    const uint32_t uVH = smem_u32(sVH), uVL = smem_u32(sVL);
    const uint32_t uPH = smem_u32(sPH), uPL = smem_u32(sPL);

    load_split64x64(qg + ((size_t)bh * NS + i0) * DD, sQH, sQL, t);

    const int arow = wm * 32 + (lane & 15);
    const int lq = lane >> 2, lr = lane & 3;

    float m_run[4], s_run[4];
    #pragma unroll
    for (int s = 0; s < 4; ++s) { m_run[s] = -INFINITY; s_run[s] = 0.f; }

    float cacc[2][2][4];
    #pragma unroll
    for (int mb = 0; mb < 2; ++mb)
        #pragma unroll
        for (int nt = 0; nt < 2; ++nt)
            #pragma unroll
            for (int e = 0; e < 4; ++e) cacc[mb][nt][e] = 0.f;

    const size_t srow_base = ((size_t)bh << 20) + (size_t)i0 * NS;

    for (int jt = 0; jt < 16; ++jt) {
        const int j0 = jt << 6;
        if (jt) __syncthreads();    // prior AV mma reads done before overwrite

        load_split64x64(kg + ((size_t)bh * NS + j0) * DD, sKH, sKL, t);
        load_split64x64(vg + ((size_t)bh * NS + j0) * DD, sVH, sVL, t);
        __syncthreads();

        // ---- QK^T MMA (bf16 3-pass) ----
        float sc[2][2][4];
        #pragma unroll
        for (int mb = 0; mb < 2; ++mb)
            #pragma unroll
            for (int nt = 0; nt < 2; ++nt)
                #pragma unroll
                for (int e = 0; e < 4; ++e) sc[mb][nt][e] = 0.f;

        #pragma unroll
        for (int ks = 0; ks < 4; ++ks) {
            const int kc = ks * 16 + ((lane >> 4) << 3);
            uint32_t aH[2][4], aL[2][4];
            #pragma unroll
            for (int mb = 0; mb < 2; ++mb) {
                uint32_t o = off64(arow + mb * 16, kc);
                ldsm4(aH[mb], uQH + o);
                ldsm4(aL[mb], uQL + o);
            }
            uint32_t bo = off64(wn * 16 + (lane & 15), kc);
            uint32_t bH[4], bL[4];
            ldsm4(bH, uKH + bo);
            ldsm4(bL, uKL + bo);
            #pragma unroll
            for (int mb = 0; mb < 2; ++mb) {
                mma16816(sc[mb][0], aH[mb], bH[0], bH[2]);
                mma16816(sc[mb][1], aH[mb], bH[1], bH[3]);
                mma16816(sc[mb][0], aH[mb], bL[0], bL[2]);
                mma16816(sc[mb][1], aH[mb], bL[1], bL[3]);
                mma16816(sc[mb][0], aL[mb], bH[0], bH[2]);
                mma16816(sc[mb][1], aL[mb], bH[1], bH[3]);
            }
        }

        // ---- scale + block-wide per-row max ----
        #pragma unroll
        for (int mb = 0; mb < 2; ++mb)
            #pragma unroll
            for (int nt = 0; nt < 2; ++nt)
                #pragma unroll
                for (int e = 0; e < 4; ++e) sc[mb][nt][e] *= 0.125f;

        float cm[4];
        #pragma unroll
        for (int mb = 0; mb < 2; ++mb)
            #pragma unroll
            for (int sl = 0; sl < 2; ++sl) {
                int slot = mb * 2 + sl;
                float c0 = fmaxf(sc[mb][0][sl * 2], sc[mb][0][sl * 2 + 1]);
                float c1 = fmaxf(sc[mb][1][sl * 2], sc[mb][1][sl * 2 + 1]);
                float c = fmaxf(c0, c1);
                c = fmaxf(c, __shfl_xor_sync(0xffffffffu, c, 1));
                c = fmaxf(c, __shfl_xor_sync(0xffffffffu, c, 2));
                cm[slot] = c;
            }
        if (lr == 0) {
            #pragma unroll
            for (int slot = 0; slot < 4; ++slot) {
                int row = wm * 32 + (slot >> 1) * 16 + (slot & 1) * 8 + lq;
                sRed[wn * 64 + row] = cm[slot];
            }
        }
        __syncthreads();

        // ---- epilogue: stats, scores write, p~ STS, ctx rescale ----
        #pragma unroll
        for (int mb = 0; mb < 2; ++mb)
            #pragma unroll
            for (int sl = 0; sl < 2; ++sl) {
                const int slot = mb * 2 + sl;
                const int row = wm * 32 + mb * 16 + sl * 8 + lq;
                float nm = m_run[slot];
                #pragma unroll
                for (int w = 0; w < 4; ++w) nm = fmaxf(nm, sRed[w * 64 + row]);
                const float f = __expf(m_run[slot] - nm);
                m_run[slot] = nm;

                float p0 = __expf(sc[mb][0][sl * 2]     - nm);
                float p1 = __expf(sc[mb][0][sl * 2 + 1] - nm);
                float p2 = __expf(sc[mb][1][sl * 2]     - nm);
                float p3 = __expf(sc[mb][1][sl * 2 + 1] - nm);
                s_run[slot] = s_run[slot] * f + (p0 + p1 + p2 + p3);

                // scores global write
                float* sp = scores + srow_base + (size_t)row * NS + j0 + wn * 16 + lr * 2;
                float2 o0; o0.x = sc[mb][0][sl * 2]; o0.y = sc[mb][0][sl * 2 + 1];
                float2 o1; o1.x = sc[mb][1][sl * 2]; o1.y = sc[mb][1][sl * 2 + 1];
                *reinterpret_cast<float2*>(sp)     = o0;
                *reinterpret_cast<float2*>(sp + 8) = o1;

                // p~ -> bf16 hi/lo smem
                uint32_t h0, l0, h1, l1;
                split2(p0, p1, h0, l0);
                split2(p2, p3, h1, l1);
                uint32_t oa = off64(row, wn * 16 + lr * 2);
                uint32_t ob = off64(row, wn * 16 + 8 + lr * 2);
                *reinterpret_cast<uint32_t*>(sPH + oa) = h0;
                *reinterpret_cast<uint32_t*>(sPL + oa) = l0;
                *reinterpret_cast<uint32_t*>(sPH + ob) = h1;
                *reinterpret_cast<uint32_t*>(sPL + ob) = l1;

                // ctx rescale
                #pragma unroll
                for (int nt = 0; nt < 2; ++nt) {
                    cacc[mb][nt][sl * 2]     *= f;
                    cacc[mb][nt][sl * 2 + 1] *= f;
                }
            }
        __syncthreads();

        // ---- AV MMA: ctx += p~ @ V (bf16 3-pass) ----
        #pragma unroll
        for (int ks = 0; ks < 4; ++ks) {
            const int kc = ks * 16 + ((lane >> 4) << 3);
            uint32_t aH[2][4], aL[2][4];
            #pragma unroll
            for (int mb = 0; mb < 2; ++mb) {
                uint32_t o = off64(arow + mb * 16, kc);
                ldsm4(aH[mb], uPH + o);
                ldsm4(aL[mb], uPL + o);
            }
            uint32_t bo = off64(ks * 16 + (lane & 15),
                                wn * 16 + ((lane >> 4) << 3));
            uint32_t bH[4], bL[4];
            ldsm4t(bH, uVH + bo);
            ldsm4t(bL, uVL + bo);
            #pragma unroll
            for (int mb = 0; mb < 2; ++mb) {
                mma16816(cacc[mb][0], aH[mb], bH[0], bH[1]);
                mma16816(cacc[mb][1], aH[mb], bH[2], bH[3]);
                mma16816(cacc[mb][0], aH[mb], bL[0], bL[1]);
                mma16816(cacc[mb][1], aH[mb], bL[2], bL[3]);
                mma16816(cacc[mb][0], aL[mb], bH[0], bH[1]);
                mma16816(cacc[mb][1], aL[mb], bH[2], bH[3]);
            }
        }
    }

    // ---- finalize stats (max trajectory shared -> plain sums) ----
    #pragma unroll
    for (int slot = 0; slot < 4; ++slot) {
        float s = s_run[slot];
        s += __shfl_xor_sync(0xffffffffu, s, 1);
        s += __shfl_xor_sync(0xffffffffu, s, 2);
        if (lr == 0) {
            int row = wm * 32 + (slot >> 1) * 16 + (slot & 1) * 8 + lq;
            sSum[wn * 64 + row] = s;
            if (wn == 0) smM[row] = m_run[slot];
        }
    }
    __syncthreads();
    if (t < 64) {
        float stot = sSum[t] + sSum[64 + t] + sSum[128 + t] + sSum[192 + t];
        smI[t] = 1.f / stot;
    }
    __syncthreads();

    // ---- normalized ctx write ----
    #pragma unroll
    for (int mb = 0; mb < 2; ++mb)
        #pragma unroll
        for (int sl = 0; sl < 2; ++sl) {
            const int row = wm * 32 + mb * 16 + sl * 8 + lq;
            const float inv = smI[row];
            float* cp = ctx + (((size_t)bh << 10) + i0 + row) * DD + wn * 16 + lr * 2;
            #pragma unroll
            for (int nt = 0; nt < 2; ++nt) {
                float2 o;
                o.x = cacc[mb][nt][sl * 2]     * inv;
                o.y = cacc[mb][nt][sl * 2 + 1] * inv;
                *reinterpret_cast<float2*>(cp + nt * 8) = o;
            }
        }

    // ---- pass 2: stream scores (L1/L2-hot) -> attn ----
    const float4* sp4 = (const float4*)(scores + srow_base);
    float4*       ap4 = (float4*)(attn + srow_base);
    #pragma unroll 4
    for (int c = 0; c < 64; ++c) {
        const float m = smM[c], inv = smI[c];
        float4 s = sp4[(c << 8) + t];
        float4 p;
        p.x = __expf(s.x - m) * inv;
        p.y = __expf(s.y - m) * inv;
        p.z = __expf(s.z - m) * inv;
        p.w = __expf(s.w - m) * inv;
        ap4[(c << 8) + t] = p;
    }
}

// ---------------------------------------------------------------------------
extern "C" void kernel_launch(void* const* d_in, const int* in_sizes, int n_in,
                              void* d_out, int out_size)
{
    const float* q = (const float*)d_in[0];
    const float* k = (const float*)d_in[1];
    const float* v = (const float*)d_in[2];

    float* out    = (float*)d_out;
    float* ctx    = out;                                  // [T,B,H,N,D]
    float* scores = out + (size_t)BHN * NS * DD;          // [T,B,H,N,N]
    float* attn   = scores + (size_t)BHN * NS * NS;       // [T,B,H,N,N]

    cudaFuncSetAttribute(fused_attn, cudaFuncAttributeMaxDynamicSharedMemorySize, F_SMEM);

    dim3 g(NS / 64, BHN);
    fused_attn<<<g, 256, F_SMEM>>>(q, k, v, scores, attn, ctx);
}